// round 10
// baseline (speedup 1.0000x reference)
#include <cuda_runtime.h>
#include <math.h>
#include <float.h>

#define N 384
#define NPIX (N*N)

// Scale index: 0->S=5, 1->S=23, 2->S=33.  Plane-major (coalesced).
__device__ float g_plane[3][9][NPIX];   // descending: plane 0 = column max
__device__ float g_colsum[3][NPIX];
__device__ float2 g_MI[3][NPIX];        // .x = M, .y = IRIL (packed: consumed together)

__device__ __forceinline__ int refl(int i) {
    if (i < 0) i = -i;
    if (i >= N) i = 2 * N - 2 - i;
    return i;
}

// Depth-2 branch-free insert into ascending 9-array (t[0] = min of kept set).
__device__ __forceinline__ void ins9_bf(float (&t)[9], float v) {
    float u  = fmaxf(v, t[0]);
    float r0 = fminf(u, t[1]);
    float r1 = fminf(fmaxf(u, t[1]), t[2]);
    float r2 = fminf(fmaxf(u, t[2]), t[3]);
    float r3 = fminf(fmaxf(u, t[3]), t[4]);
    float r4 = fminf(fmaxf(u, t[4]), t[5]);
    float r5 = fminf(fmaxf(u, t[5]), t[6]);
    float r6 = fminf(fmaxf(u, t[6]), t[7]);
    float r7 = fminf(fmaxf(u, t[7]), t[8]);
    float r8 = fmaxf(u, t[8]);
    t[0] = r0; t[1] = r1; t[2] = r2; t[3] = r3; t[4] = r4;
    t[5] = r5; t[6] = r6; t[7] = r7; t[8] = r8;
}

// ---------------------------------------------------------------------------
// K1: fused column pass (frozen — measured ~10us).
// ---------------------------------------------------------------------------
__global__ __launch_bounds__(256) void colpass_all(const float* __restrict__ x) {
    int idx = blockIdx.x * blockDim.x + threadIdx.x;
    if (idx >= NPIX) return;
    int iy = idx / N, ix = idx % N;

    float t[9];
#pragma unroll
    for (int i = 0; i < 9; i++) t[i] = -FLT_MAX;
    float sum = 0.0f;

#pragma unroll
    for (int k = 0; k < 33; k++) {
        int mag = (k + 1) >> 1;
        int dy = (k & 1) ? -mag : mag;          // 0,-1,+1,-2,+2,...
        int yy = refl(iy + dy);
        float v = 255.0f * __ldg(&x[yy * N + ix]);
        sum += v;
        ins9_bf(t, v);
        if (k == 4 || k == 22 || k == 32) {
            int s = (k == 4) ? 0 : (k == 22) ? 1 : 2;
#pragma unroll
            for (int p = 0; p < 9; p++) g_plane[s][p][idx] = t[8 - p];  // descending
            g_colsum[s][idx] = sum;
        }
    }
}

// ---------------------------------------------------------------------------
// Sorted-descending 9-list merge machinery (frozen — R9 win).
// ---------------------------------------------------------------------------
__device__ __forceinline__ void ced(float& x, float& y) {
    float hi = fmaxf(x, y), lo = fminf(x, y);
    x = hi; y = lo;
}

__device__ __forceinline__ void merge9_sorted(const float* A, const float* B, float* O) {
    float v0 = fmaxf(A[0], B[8]);
    float v1 = fmaxf(A[1], B[7]);
    float v2 = fmaxf(A[2], B[6]);
    float v3 = fmaxf(A[3], B[5]);
    float v4 = fmaxf(A[4], B[4]);
    float v5 = fmaxf(A[5], B[3]);
    float v6 = fmaxf(A[6], B[2]);
    float v7 = fmaxf(A[7], B[1]);
    float v8 = fmaxf(A[8], B[0]);
    ced(v0, v8);
    ced(v1, v5); ced(v2, v6); ced(v3, v7); ced(v4, v8);
    ced(v1, v3); ced(v2, v4); ced(v5, v7); ced(v6, v8);
    ced(v1, v2); ced(v3, v4); ced(v5, v6); ced(v7, v8);
    O[0] = v0; O[1] = v1; O[2] = v2; O[3] = v3; O[4] = v4;
    O[5] = v5; O[6] = v6; O[7] = v7; O[8] = v8;
}

__device__ __forceinline__ float merge9_sum(const float* A, const float* B) {
    float s = fmaxf(A[0], B[8]);
    s += fmaxf(A[1], B[7]);
    s += fmaxf(A[2], B[6]);
    s += fmaxf(A[3], B[5]);
    s += fmaxf(A[4], B[4]);
    s += fmaxf(A[5], B[3]);
    s += fmaxf(A[6], B[2]);
    s += fmaxf(A[7], B[1]);
    s += fmaxf(A[8], B[0]);
    return s;
}

// ---------------------------------------------------------------------------
// K2: row merge via sparse-table levels (structure frozen; output now float2).
// ---------------------------------------------------------------------------
#define RW 128
#define HALO 16
#define RC (RW + 2*HALO)   // 160

template <int S, int SC, int TOPL>
__device__ __forceinline__ void gw_scale(
    float (&sL)[6][RC][9], float (&sS)[6][RC],
    int row, int colbase, int tid)
{
    {
        const float* cs = &g_colsum[SC][row * N];
        for (int i = tid; i < RC; i += RW)
            sS[0][i] = __ldg(&cs[refl(colbase - HALO + i)]);
#pragma unroll
        for (int p = 0; p < 9; p++) {
            const float* pl = &g_plane[SC][p][row * N];
            for (int i = tid; i < RC; i += RW)
                sL[0][i][p] = __ldg(&pl[refl(colbase - HALO + i)]);
        }
    }
    __syncthreads();

#pragma unroll
    for (int k = 1; k <= TOPL; k++) {
        const int d = 1 << (k - 1);
        const int lim = RC - (1 << k) + 1;
        for (int i = tid; i < lim; i += RW) {
            merge9_sorted(sL[k - 1][i], sL[k - 1][i + d], sL[k][i]);
            sS[k][i] = sS[k - 1][i] + sS[k - 1][i + d];
        }
        __syncthreads();
    }

    float sum9, wsum;
    if (S == 33) {
        int a = tid;
        sum9 = merge9_sum(sL[5][a], sL[0][a + 32]);
        wsum = sS[5][a] + sS[0][a + 32];
    } else if (S == 23) {
        int a = tid + 5;
        float E[9], F[9];
        merge9_sorted(sL[4][a],      sL[2][a + 16], E);
        merge9_sorted(sL[1][a + 20], sL[0][a + 22], F);
        sum9 = merge9_sum(E, F);
        wsum = sS[4][a] + sS[2][a + 16] + sS[1][a + 20] + sS[0][a + 22];
    } else {
        int a = tid + 14;
        sum9 = merge9_sum(sL[2][a], sL[0][a + 4]);
        wsum = sS[2][a] + sS[0][a + 4];
    }

    float M = sum9 * (1.0f / 9.0f);
    float avg = wsum * (1.0f / (float)(S * S));
    int idx = row * N + colbase + tid;
    g_MI[SC][idx] = make_float2(M, M - avg);
}

__global__ __launch_bounds__(RW) void rowpass_all() {
    __shared__ float sL[6][RC][9];
    __shared__ float sS[6][RC];
    int row = blockIdx.y;
    int colbase = blockIdx.x * RW;
    int tid = threadIdx.x;

    if      (blockIdx.z == 0) gw_scale<5, 0, 2>(sL, sS, row, colbase, tid);
    else if (blockIdx.z == 1) gw_scale<23, 1, 4>(sL, sS, row, colbase, tid);
    else                      gw_scale<33, 2, 5>(sL, sS, row, colbase, tid);
}

// ---------------------------------------------------------------------------
// K3: fused combine — float2 loads: 9 LDG.64 per scale instead of 17 LDG.32.
// ---------------------------------------------------------------------------
template <int D, int SC>
__device__ __forceinline__ float combine_one(int iy, int ix, float gg) {
    float BE = -FLT_MAX;
    float ni[9];
#pragma unroll
    for (int i = 0; i < 3; i++) {
        int yy = refl(iy + (i - 1) * D);
#pragma unroll
        for (int j = 0; j < 3; j++) {
            int xx = refl(ix + (j - 1) * D);
            float2 mi = __ldg(&g_MI[SC][yy * N + xx]);
            ni[i * 3 + j] = mi.y;
            if (!(i == 1 && j == 1)) BE = fmaxf(BE, mi.x);
        }
    }

    float SLCM = fmaxf((BE / gg - 1.0f) * gg, 0.0f);

    float WT = ni[4];
    float mx = -FLT_MAX;
    float s = 0.0f;
#pragma unroll
    for (int k = 0; k < 9; k++) {
        if (k == 4) continue;
        mx = fmaxf(mx, ni[k]);
        s += ni[k];
    }
    float mean = s * 0.125f;
    float ss = 0.0f;
#pragma unroll
    for (int k = 0; k < 9; k++) {
        if (k == 4) continue;
        float d = ni[k] - mean;
        ss += d * d;
    }
    float WB = fmaxf(sqrtf(ss * (1.0f / 7.0f)), 5.0f);
    float WD = fmaxf(WT - mx, 0.0f);
    return SLCM * WT * WD / WB;
}

__global__ __launch_bounds__(256) void combine_all(const float* __restrict__ x,
                                                   float* __restrict__ out) {
    int idx = blockIdx.x * blockDim.x + threadIdx.x;
    if (idx >= NPIX) return;
    int iy = idx / N, ix = idx % N;

    const float kw[3] = {1.0f, 2.0f, 1.0f};
    float acc = 0.0f;
#pragma unroll
    for (int dy = -1; dy <= 1; dy++) {
        int yy = refl(iy + dy);
#pragma unroll
        for (int dx = -1; dx <= 1; dx++) {
            int xx = refl(ix + dx);
            acc += kw[dy + 1] * kw[dx + 1] * __ldg(&x[yy * N + xx]);
        }
    }
    float gg = acc * (255.0f / 16.0f) + 1.0f;

    float r = 0.0f;                                 // scale-3 branch is exactly 0
    r = fmaxf(r, combine_one<5, 0>(iy, ix, gg));
    r = fmaxf(r, combine_one<23, 1>(iy, ix, gg));
    r = fmaxf(r, combine_one<33, 2>(iy, ix, gg));
    out[idx] = r;
}

// ---------------------------------------------------------------------------
extern "C" void kernel_launch(void* const* d_in, const int* in_sizes, int n_in,
                              void* d_out, int out_size) {
    const float* x = (const float*)d_in[0];
    float* out = (float*)d_out;

    colpass_all<<<(NPIX + 255) / 256, 256>>>(x);

    dim3 rgrid(N / RW, N, 3);
    rowpass_all<<<rgrid, RW>>>();

    combine_all<<<(NPIX + 255) / 256, 256>>>(x, out);
}

// round 11
// speedup vs baseline: 2.0000x; 2.0000x over previous
#include <cuda_runtime.h>
#include <math.h>
#include <float.h>

#define N 384
#define NPIX (N*N)

// Only surviving intermediate: M/IRIL packed per scale (consumed by combine).
__device__ float2 g_MI[3][NPIX];        // .x = M, .y = IRIL

__device__ __forceinline__ int refl(int i) {
    if (i < 0) i = -i;
    if (i >= N) i = 2 * N - 2 - i;
    return i;
}

// Depth-2 branch-free insert into ascending 9-array (t[0] = min of kept set).
__device__ __forceinline__ void ins9_bf(float (&t)[9], float v) {
    float u  = fmaxf(v, t[0]);
    float r0 = fminf(u, t[1]);
    float r1 = fminf(fmaxf(u, t[1]), t[2]);
    float r2 = fminf(fmaxf(u, t[2]), t[3]);
    float r3 = fminf(fmaxf(u, t[3]), t[4]);
    float r4 = fminf(fmaxf(u, t[4]), t[5]);
    float r5 = fminf(fmaxf(u, t[5]), t[6]);
    float r6 = fminf(fmaxf(u, t[6]), t[7]);
    float r7 = fminf(fmaxf(u, t[7]), t[8]);
    float r8 = fmaxf(u, t[8]);
    t[0] = r0; t[1] = r1; t[2] = r2; t[3] = r3; t[4] = r4;
    t[5] = r5; t[6] = r6; t[7] = r7; t[8] = r8;
}

// Sorted-descending 9-list merge: m[i]=max(A[i],B[8-i]) is the top-9 multiset
// and is V-shaped (bitonic); 13-CE network sorts it.
__device__ __forceinline__ void ced(float& x, float& y) {
    float hi = fmaxf(x, y), lo = fminf(x, y);
    x = hi; y = lo;
}

__device__ __forceinline__ void merge9_sorted(const float* A, const float* B, float* O) {
    float v0 = fmaxf(A[0], B[8]);
    float v1 = fmaxf(A[1], B[7]);
    float v2 = fmaxf(A[2], B[6]);
    float v3 = fmaxf(A[3], B[5]);
    float v4 = fmaxf(A[4], B[4]);
    float v5 = fmaxf(A[5], B[3]);
    float v6 = fmaxf(A[6], B[2]);
    float v7 = fmaxf(A[7], B[1]);
    float v8 = fmaxf(A[8], B[0]);
    ced(v0, v8);
    ced(v1, v5); ced(v2, v6); ced(v3, v7); ced(v4, v8);
    ced(v1, v3); ced(v2, v4); ced(v5, v7); ced(v6, v8);
    ced(v1, v2); ced(v3, v4); ced(v5, v6); ced(v7, v8);
    O[0] = v0; O[1] = v1; O[2] = v2; O[3] = v3; O[4] = v4;
    O[5] = v5; O[6] = v6; O[7] = v7; O[8] = v8;
}

__device__ __forceinline__ float merge9_sum(const float* A, const float* B) {
    float s = fmaxf(A[0], B[8]);
    s += fmaxf(A[1], B[7]);
    s += fmaxf(A[2], B[6]);
    s += fmaxf(A[3], B[5]);
    s += fmaxf(A[4], B[4]);
    s += fmaxf(A[5], B[3]);
    s += fmaxf(A[6], B[2]);
    s += fmaxf(A[7], B[1]);
    s += fmaxf(A[8], B[0]);
    return s;
}

// ---------------------------------------------------------------------------
// K1 (fused): vertical scan + horizontal sparse-table merge, one block =
// 128 outputs of one row, 160 threads = one per halo-inclusive column.
// No global intermediates for column lists.
// ---------------------------------------------------------------------------
#define RW 128
#define HALO 16
#define RC (RW + 2*HALO)   // 160

// smem: L0 snapshots per scale + levels 1..4 (S=33's L5 folded into query).
struct RowSmem {
    float L0[3][RC][9];   // per-scale column top-9, descending
    float S0[3][RC];      // per-scale column sums
    float sL[4][RC][9];   // levels 1..4 (k-1 indexed), rebuilt per scale
    float sS[4][RC];
};                         // 44.7 KB

template <int S, int SC, int TOPL>
__device__ __forceinline__ void process_scale(RowSmem& sm, int row, int colbase, int tid) {
    // Build levels 1..TOPL from this scale's L0.
#pragma unroll
    for (int k = 1; k <= TOPL; k++) {
        const int d = 1 << (k - 1);
        const int lim = RC - (1 << k) + 1;
        if (tid < lim) {
            const float* a  = (k == 1) ? sm.L0[SC][tid]     : sm.sL[k - 2][tid];
            const float* b  = (k == 1) ? sm.L0[SC][tid + d] : sm.sL[k - 2][tid + d];
            merge9_sorted(a, b, sm.sL[k - 1][tid]);
            float sa = (k == 1) ? sm.S0[SC][tid]     : sm.sS[k - 2][tid];
            float sb = (k == 1) ? sm.S0[SC][tid + d] : sm.sS[k - 2][tid + d];
            sm.sS[k - 1][tid] = sa + sb;
        }
        __syncthreads();
    }

    if (tid < RW) {
        float sum9, wsum;
        if (S == 33) {
            int a = tid;                       // P=16
            float E[9];
            merge9_sorted(sm.sL[3][a], sm.sL[3][a + 16], E);   // L5[a] on the fly
            sum9 = merge9_sum(E, sm.L0[SC][a + 32]);
            wsum = sm.sS[3][a] + sm.sS[3][a + 16] + sm.S0[SC][a + 32];
        } else if (S == 23) {
            int a = tid + 5;                   // P=11: L4 + L2 + L1 + L0
            float E[9], F[9];
            merge9_sorted(sm.sL[3][a],      sm.sL[1][a + 16], E);
            merge9_sorted(sm.sL[0][a + 20], sm.L0[SC][a + 22], F);
            sum9 = merge9_sum(E, F);
            wsum = sm.sS[3][a] + sm.sS[1][a + 16] + sm.sS[0][a + 20] + sm.S0[SC][a + 22];
        } else {
            int a = tid + 14;                  // P=2: L2 + L0
            sum9 = merge9_sum(sm.sL[1][a], sm.L0[SC][a + 4]);
            wsum = sm.sS[1][a] + sm.S0[SC][a + 4];
        }
        float M = sum9 * (1.0f / 9.0f);
        float avg = wsum * (1.0f / (float)(S * S));
        g_MI[SC][row * N + colbase + tid] = make_float2(M, M - avg);
    }
    __syncthreads();   // protect sL before next scale rebuilds
}

__global__ __launch_bounds__(RC) void rowfused(const float* __restrict__ x) {
    __shared__ RowSmem sm;
    const int row = blockIdx.y;
    const int colbase = blockIdx.x * RW;
    const int tid = threadIdx.x;
    const int gc = refl(colbase - HALO + tid);

    // Vertical 33-scan for this column, snapshots at S=5, 23, 33.
    float t[9];
#pragma unroll
    for (int i = 0; i < 9; i++) t[i] = -FLT_MAX;
    float sum = 0.0f;

#pragma unroll
    for (int k = 0; k < 33; k++) {
        int mag = (k + 1) >> 1;
        int dy = (k & 1) ? -mag : mag;          // 0,-1,+1,-2,+2,...
        int yy = refl(row + dy);
        float v = 255.0f * __ldg(&x[yy * N + gc]);
        sum += v;
        ins9_bf(t, v);
        if (k == 4 || k == 22 || k == 32) {
            int s = (k == 4) ? 0 : (k == 22) ? 1 : 2;
#pragma unroll
            for (int p = 0; p < 9; p++) sm.L0[s][tid][p] = t[8 - p];  // descending
            sm.S0[s][tid] = sum;
        }
    }
    __syncthreads();

    process_scale<33, 2, 4>(sm, row, colbase, tid);
    process_scale<23, 1, 4>(sm, row, colbase, tid);
    process_scale<5, 0, 2>(sm, row, colbase, tid);
}

// ---------------------------------------------------------------------------
// K2: fused combine (frozen).
// ---------------------------------------------------------------------------
template <int D, int SC>
__device__ __forceinline__ float combine_one(int iy, int ix, float gg) {
    float BE = -FLT_MAX;
    float ni[9];
#pragma unroll
    for (int i = 0; i < 3; i++) {
        int yy = refl(iy + (i - 1) * D);
#pragma unroll
        for (int j = 0; j < 3; j++) {
            int xx = refl(ix + (j - 1) * D);
            float2 mi = __ldg(&g_MI[SC][yy * N + xx]);
            ni[i * 3 + j] = mi.y;
            if (!(i == 1 && j == 1)) BE = fmaxf(BE, mi.x);
        }
    }

    float SLCM = fmaxf((BE / gg - 1.0f) * gg, 0.0f);

    float WT = ni[4];
    float mx = -FLT_MAX;
    float s = 0.0f;
#pragma unroll
    for (int k = 0; k < 9; k++) {
        if (k == 4) continue;
        mx = fmaxf(mx, ni[k]);
        s += ni[k];
    }
    float mean = s * 0.125f;
    float ss = 0.0f;
#pragma unroll
    for (int k = 0; k < 9; k++) {
        if (k == 4) continue;
        float d = ni[k] - mean;
        ss += d * d;
    }
    float WB = fmaxf(sqrtf(ss * (1.0f / 7.0f)), 5.0f);
    float WD = fmaxf(WT - mx, 0.0f);
    return SLCM * WT * WD / WB;
}

__global__ __launch_bounds__(256) void combine_all(const float* __restrict__ x,
                                                   float* __restrict__ out) {
    int idx = blockIdx.x * blockDim.x + threadIdx.x;
    if (idx >= NPIX) return;
    int iy = idx / N, ix = idx % N;

    const float kw[3] = {1.0f, 2.0f, 1.0f};
    float acc = 0.0f;
#pragma unroll
    for (int dy = -1; dy <= 1; dy++) {
        int yy = refl(iy + dy);
#pragma unroll
        for (int dx = -1; dx <= 1; dx++) {
            int xx = refl(ix + dx);
            acc += kw[dy + 1] * kw[dx + 1] * __ldg(&x[yy * N + xx]);
        }
    }
    float gg = acc * (255.0f / 16.0f) + 1.0f;

    float r = 0.0f;                                 // scale-3 branch is exactly 0
    r = fmaxf(r, combine_one<5, 0>(iy, ix, gg));
    r = fmaxf(r, combine_one<23, 1>(iy, ix, gg));
    r = fmaxf(r, combine_one<33, 2>(iy, ix, gg));
    out[idx] = r;
}

// ---------------------------------------------------------------------------
extern "C" void kernel_launch(void* const* d_in, const int* in_sizes, int n_in,
                              void* d_out, int out_size) {
    const float* x = (const float*)d_in[0];
    float* out = (float*)d_out;

    dim3 rgrid(N / RW, N);
    rowfused<<<rgrid, RC>>>(x);

    combine_all<<<(NPIX + 255) / 256, 256>>>(x, out);
}

// round 12
// speedup vs baseline: 2.1664x; 1.0832x over previous
#include <cuda_runtime.h>
#include <math.h>
#include <float.h>

#define N 384
#define NPIX (N*N)

// Only surviving intermediate: M/IRIL packed per scale (consumed by combine).
__device__ float2 g_MI[3][NPIX];        // .x = M, .y = IRIL

__device__ __forceinline__ int refl(int i) {
    if (i < 0) i = -i;
    if (i >= N) i = 2 * N - 2 - i;
    return i;
}

// Compare-exchange, descending (max first).
__device__ __forceinline__ void ced(float& x, float& y) {
    float hi = fmaxf(x, y), lo = fminf(x, y);
    x = hi; y = lo;
}

// Batcher sort-8, descending.
__device__ __forceinline__ void sort8_desc(float* v) {
    ced(v[0],v[1]); ced(v[2],v[3]); ced(v[4],v[5]); ced(v[6],v[7]);
    ced(v[0],v[2]); ced(v[1],v[3]); ced(v[4],v[6]); ced(v[5],v[7]);
    ced(v[1],v[2]); ced(v[5],v[6]);
    ced(v[0],v[4]); ced(v[1],v[5]); ced(v[2],v[6]); ced(v[3],v[7]);
    ced(v[2],v[4]); ced(v[3],v[5]);
    ced(v[1],v[2]); ced(v[3],v[4]); ced(v[5],v[6]);
}

// Sort-9 desc = sort-8 + bubble-insert of v[8].
__device__ __forceinline__ void sort9_desc(float* v) {
    sort8_desc(v);
    ced(v[7],v[8]); ced(v[6],v[7]); ced(v[5],v[6]); ced(v[4],v[5]);
    ced(v[3],v[4]); ced(v[2],v[3]); ced(v[1],v[2]); ced(v[0],v[1]);
}

// Insert value into sorted-desc 9-list keeping top-9 (drops the min).
__device__ __forceinline__ void top9_insert_desc(float* d, float v) {
    d[8] = fmaxf(d[8], v);
    ced(d[7],d[8]); ced(d[6],d[7]); ced(d[5],d[6]); ced(d[4],d[5]);
    ced(d[3],d[4]); ced(d[2],d[3]); ced(d[1],d[2]); ced(d[0],d[1]);
}

// Sorted-desc 9-list merge: m[i]=max(A[i],B[8-i]) is the top-9 multiset and is
// V-shaped (bitonic); 13-CE network sorts it. (Validated R9.)
__device__ __forceinline__ void merge9_sorted(const float* A, const float* B, float* O) {
    float v0 = fmaxf(A[0], B[8]);
    float v1 = fmaxf(A[1], B[7]);
    float v2 = fmaxf(A[2], B[6]);
    float v3 = fmaxf(A[3], B[5]);
    float v4 = fmaxf(A[4], B[4]);
    float v5 = fmaxf(A[5], B[3]);
    float v6 = fmaxf(A[6], B[2]);
    float v7 = fmaxf(A[7], B[1]);
    float v8 = fmaxf(A[8], B[0]);
    ced(v0, v8);
    ced(v1, v5); ced(v2, v6); ced(v3, v7); ced(v4, v8);
    ced(v1, v3); ced(v2, v4); ced(v5, v7); ced(v6, v8);
    ced(v1, v2); ced(v3, v4); ced(v5, v6); ced(v7, v8);
    O[0] = v0; O[1] = v1; O[2] = v2; O[3] = v3; O[4] = v4;
    O[5] = v5; O[6] = v6; O[7] = v7; O[8] = v8;
}

__device__ __forceinline__ float merge9_sum(const float* A, const float* B) {
    float s = fmaxf(A[0], B[8]);
    s += fmaxf(A[1], B[7]);
    s += fmaxf(A[2], B[6]);
    s += fmaxf(A[3], B[5]);
    s += fmaxf(A[4], B[4]);
    s += fmaxf(A[5], B[3]);
    s += fmaxf(A[6], B[2]);
    s += fmaxf(A[7], B[1]);
    s += fmaxf(A[8], B[0]);
    return s;
}

// ---------------------------------------------------------------------------
// K1 (fused): group-sorted vertical scan + horizontal sparse-table merge.
// Block = 128 outputs of one row; 160 threads = one per halo column.
// Values are UNSCALED x (255 factor folded into M/avg — max is order-
// preserving under positive scaling).
// ---------------------------------------------------------------------------
#define RW 128
#define HALO 16
#define RC (RW + 2*HALO)   // 160

struct RowSmem {
    float L0[3][RC][9];   // per-scale column top-9, descending
    float S0[3][RC];      // per-scale column sums
    float sL[4][RC][9];   // levels 1..4 (k-1 indexed), rebuilt per scale
    float sS[4][RC];
};                         // 44.7 KB

template <int S, int SC, int TOPL>
__device__ __forceinline__ void process_scale(RowSmem& sm, int row, int colbase, int tid) {
#pragma unroll
    for (int k = 1; k <= TOPL; k++) {
        const int d = 1 << (k - 1);
        const int lim = RC - (1 << k) + 1;
        if (tid < lim) {
            const float* a  = (k == 1) ? sm.L0[SC][tid]     : sm.sL[k - 2][tid];
            const float* b  = (k == 1) ? sm.L0[SC][tid + d] : sm.sL[k - 2][tid + d];
            merge9_sorted(a, b, sm.sL[k - 1][tid]);
            float sa = (k == 1) ? sm.S0[SC][tid]     : sm.sS[k - 2][tid];
            float sb = (k == 1) ? sm.S0[SC][tid + d] : sm.sS[k - 2][tid + d];
            sm.sS[k - 1][tid] = sa + sb;
        }
        __syncthreads();
    }

    if (tid < RW) {
        float sum9, wsum;
        if (S == 33) {
            int a = tid;                       // P=16
            float E[9];
            merge9_sorted(sm.sL[3][a], sm.sL[3][a + 16], E);   // L5 on the fly
            sum9 = merge9_sum(E, sm.L0[SC][a + 32]);
            wsum = sm.sS[3][a] + sm.sS[3][a + 16] + sm.S0[SC][a + 32];
        } else if (S == 23) {
            int a = tid + 5;                   // P=11: L4 + L2 + L1 + L0
            float E[9], F[9];
            merge9_sorted(sm.sL[3][a],      sm.sL[1][a + 16], E);
            merge9_sorted(sm.sL[0][a + 20], sm.L0[SC][a + 22], F);
            sum9 = merge9_sum(E, F);
            wsum = sm.sS[3][a] + sm.sS[1][a + 16] + sm.sS[0][a + 20] + sm.S0[SC][a + 22];
        } else {
            int a = tid + 14;                  // P=2: L2 + L0
            sum9 = merge9_sum(sm.sL[1][a], sm.L0[SC][a + 4]);
            wsum = sm.sS[1][a] + sm.S0[SC][a + 4];
        }
        float M = sum9 * (255.0f / 9.0f);                       // scale here
        float avg = wsum * (255.0f / (float)(S * S));
        g_MI[SC][row * N + colbase + tid] = make_float2(M, M - avg);
    }
    __syncthreads();
}

__global__ __launch_bounds__(RC) void rowfused(const float* __restrict__ x) {
    __shared__ RowSmem sm;
    const int row = blockIdx.y;
    const int colbase = blockIdx.x * RW;
    const int tid = threadIdx.x;
    const int gc = refl(colbase - HALO + tid);

    // --- G1: dy in [-2,2] -> S=5 snapshot ---
    float g1[9];
#pragma unroll
    for (int i = 0; i < 5; i++) g1[i] = __ldg(&x[refl(row + i - 2) * N + gc]);
    float sum5 = ((g1[0] + g1[1]) + (g1[2] + g1[3])) + g1[4];
    // sort4 + bubble-insert = sort5 desc
    ced(g1[0],g1[1]); ced(g1[2],g1[3]); ced(g1[0],g1[2]); ced(g1[1],g1[3]); ced(g1[1],g1[2]);
    ced(g1[3],g1[4]); ced(g1[2],g1[3]); ced(g1[1],g1[2]); ced(g1[0],g1[1]);
#pragma unroll
    for (int i = 5; i < 9; i++) g1[i] = -FLT_MAX;
#pragma unroll
    for (int p = 0; p < 9; p++) sm.L0[0][tid][p] = g1[p];
    sm.S0[0][tid] = sum5;

    // --- G2: dy in [-11,-3] and [3,11] -> S=23 snapshot ---
    float A[9], B[9];
#pragma unroll
    for (int i = 0; i < 9; i++) A[i] = __ldg(&x[refl(row - 11 + i) * N + gc]);
#pragma unroll
    for (int i = 0; i < 9; i++) B[i] = __ldg(&x[refl(row + 3 + i) * N + gc]);
    float sumA = 0.0f, sumB = 0.0f;
#pragma unroll
    for (int i = 0; i < 9; i++) { sumA += A[i]; sumB += B[i]; }
    sort9_desc(A);
    sort9_desc(B);
    float g2[9], s23[9];
    merge9_sorted(A, B, g2);
    merge9_sorted(g1, g2, s23);
    float sum23 = sum5 + sumA + sumB;
#pragma unroll
    for (int p = 0; p < 9; p++) sm.L0[1][tid][p] = s23[p];
    sm.S0[1][tid] = sum23;

    // --- G3: dy in [-16,-12] and [12,16] (10 elems) -> S=33 snapshot ---
    float C[9];
#pragma unroll
    for (int i = 0; i < 5; i++) C[i] = __ldg(&x[refl(row - 16 + i) * N + gc]);
#pragma unroll
    for (int i = 0; i < 4; i++) C[5 + i] = __ldg(&x[refl(row + 12 + i) * N + gc]);
    float cv = __ldg(&x[refl(row + 16) * N + gc]);
    float sumC = (((C[0] + C[1]) + (C[2] + C[3])) + ((C[4] + C[5]) + (C[6] + C[7]))) + C[8] + cv;
    sort9_desc(C);
    top9_insert_desc(C, cv);
    float s33[9];
    merge9_sorted(s23, C, s33);
#pragma unroll
    for (int p = 0; p < 9; p++) sm.L0[2][tid][p] = s33[p];
    sm.S0[2][tid] = sum23 + sumC;

    __syncthreads();

    process_scale<33, 2, 4>(sm, row, colbase, tid);
    process_scale<23, 1, 4>(sm, row, colbase, tid);
    process_scale<5, 0, 2>(sm, row, colbase, tid);
}

// ---------------------------------------------------------------------------
// K2: fused combine (frozen).
// ---------------------------------------------------------------------------
template <int D, int SC>
__device__ __forceinline__ float combine_one(int iy, int ix, float gg) {
    float BE = -FLT_MAX;
    float ni[9];
#pragma unroll
    for (int i = 0; i < 3; i++) {
        int yy = refl(iy + (i - 1) * D);
#pragma unroll
        for (int j = 0; j < 3; j++) {
            int xx = refl(ix + (j - 1) * D);
            float2 mi = __ldg(&g_MI[SC][yy * N + xx]);
            ni[i * 3 + j] = mi.y;
            if (!(i == 1 && j == 1)) BE = fmaxf(BE, mi.x);
        }
    }

    float SLCM = fmaxf((BE / gg - 1.0f) * gg, 0.0f);

    float WT = ni[4];
    float mx = -FLT_MAX;
    float s = 0.0f;
#pragma unroll
    for (int k = 0; k < 9; k++) {
        if (k == 4) continue;
        mx = fmaxf(mx, ni[k]);
        s += ni[k];
    }
    float mean = s * 0.125f;
    float ss = 0.0f;
#pragma unroll
    for (int k = 0; k < 9; k++) {
        if (k == 4) continue;
        float d = ni[k] - mean;
        ss += d * d;
    }
    float WB = fmaxf(sqrtf(ss * (1.0f / 7.0f)), 5.0f);
    float WD = fmaxf(WT - mx, 0.0f);
    return SLCM * WT * WD / WB;
}

__global__ __launch_bounds__(256) void combine_all(const float* __restrict__ x,
                                                   float* __restrict__ out) {
    int idx = blockIdx.x * blockDim.x + threadIdx.x;
    if (idx >= NPIX) return;
    int iy = idx / N, ix = idx % N;

    const float kw[3] = {1.0f, 2.0f, 1.0f};
    float acc = 0.0f;
#pragma unroll
    for (int dy = -1; dy <= 1; dy++) {
        int yy = refl(iy + dy);
#pragma unroll
        for (int dx = -1; dx <= 1; dx++) {
            int xx = refl(ix + dx);
            acc += kw[dy + 1] * kw[dx + 1] * __ldg(&x[yy * N + xx]);
        }
    }
    float gg = acc * (255.0f / 16.0f) + 1.0f;

    float r = 0.0f;                                 // scale-3 branch is exactly 0
    r = fmaxf(r, combine_one<5, 0>(iy, ix, gg));
    r = fmaxf(r, combine_one<23, 1>(iy, ix, gg));
    r = fmaxf(r, combine_one<33, 2>(iy, ix, gg));
    out[idx] = r;
}

// ---------------------------------------------------------------------------
extern "C" void kernel_launch(void* const* d_in, const int* in_sizes, int n_in,
                              void* d_out, int out_size) {
    const float* x = (const float*)d_in[0];
    float* out = (float*)d_out;

    dim3 rgrid(N / RW, N);
    rowfused<<<rgrid, RC>>>(x);

    combine_all<<<(NPIX + 255) / 256, 256>>>(x, out);
}